// round 1
// baseline (speedup 1.0000x reference)
#include <cuda_runtime.h>
#include <math_constants.h>

// Problem constants
#define T_LEN   4096
#define BATCH   32
#define DMODEL  256
#define NSTATE  64
#define CHUNK   512    // timesteps staged in smem per outer iteration

// pooled[b][0:256]=avg, pooled[b][256:512]=max
__device__ float g_pooled[BATCH * 2 * DMODEL];

using ull = unsigned long long;

// ---- f32x2 helpers (sm_100+ packed fp32: 2x FMA throughput per instr) ----
__device__ __forceinline__ ull pack2(float lo, float hi) {
    ull r; asm("mov.b64 %0, {%1, %2};" : "=l"(r) : "f"(lo), "f"(hi)); return r;
}
__device__ __forceinline__ ull bcast2(float x) {
    ull r; asm("mov.b64 %0, {%1, %1};" : "=l"(r) : "f"(x)); return r;
}
__device__ __forceinline__ ull fma2(ull a, ull b, ull c) {
    ull r; asm("fma.rn.f32x2 %0, %1, %2, %3;" : "=l"(r) : "l"(a), "l"(b), "l"(c)); return r;
}
__device__ __forceinline__ ull mul2(ull a, ull b) {
    ull r; asm("mul.rn.f32x2 %0, %1, %2;" : "=l"(r) : "l"(a), "l"(b)); return r;
}
__device__ __forceinline__ ull add2(ull a, ull b) {
    ull r; asm("add.rn.f32x2 %0, %1, %2;" : "=l"(r) : "l"(a), "l"(b)); return r;
}
__device__ __forceinline__ float2 unpack2(ull a) {
    float2 f; asm("mov.b64 {%0, %1}, %2;" : "=f"(f.x), "=f"(f.y) : "l"(a)); return f;
}

// tanh-approx gelu matching jax.nn.gelu(approximate=True)
__device__ __forceinline__ float gelu_tanh(float y) {
    float y2 = y * y;
    float inner = 0.7978845608028654f * y * fmaf(0.044715f, y2, 1.0f);
    float e = __expf(2.0f * inner);                 // MUFU path
    float r = __fdividef(1.0f, 1.0f + e);           // (1-tanh)/2
    return y - y * r;                               // 0.5*y*(1+tanh)
}

// One warp-group of 4 lanes handles one (b,d) pair; each lane owns 16 states
// packed into 8 f32x2 registers. Rescaled recurrence: v' = a*v' + u,
// y_ssm = sum_n (B_n*C_n) * v'_n.
__global__ void __launch_bounds__(64)
ssm_scan_kernel(const float* __restrict__ x,
                const float* __restrict__ w_in,
                const float* __restrict__ b_in,
                const float* __restrict__ A_diag,
                const float* __restrict__ B_in,
                const float* __restrict__ C_out,
                const float* __restrict__ D_skip)
{
    __shared__ float4 xs4[CHUNK / 4];

    const int tid = threadIdx.x;                 // 0..63
    const int b   = blockIdx.x >> 4;             // 512 blocks: 16 per batch row
    const int d   = ((blockIdx.x & 15) << 4) + (tid >> 2);
    const int q   = tid & 3;                     // n-quarter within group

    const float wd  = w_in[d];
    const float bd  = b_in[d];
    const float dsk = D_skip[d];

    ull a2[8], cb2[8], v2[8];
    {
        const int base = d * NSTATE + q * 16;
        #pragma unroll
        for (int i = 0; i < 8; i++) {
            float a0 = A_diag[base + 2 * i];
            float a1 = A_diag[base + 2 * i + 1];
            float c0 = B_in[base + 2 * i]     * C_out[base + 2 * i];
            float c1 = B_in[base + 2 * i + 1] * C_out[base + 2 * i + 1];
            a2[i]  = pack2(a0, a1);
            cb2[i] = pack2(c0, c1);
            v2[i]  = 0ull;                       // (0.0f, 0.0f)
        }
    }

    const bool is0 = (q == 0), is1 = (q == 1), is2 = (q == 2), is3 = (q == 3);

    float asum = 0.0f;
    float amax = -CUDART_INF_F;
    float ykeep = 0.0f;

    const float* xb = x + b * T_LEN;

    for (int t0 = 0; t0 < T_LEN; t0 += CHUNK) {
        // stage CHUNK timesteps of this batch row into smem
        const float4* src = reinterpret_cast<const float4*>(xb + t0);
        xs4[tid]      = src[tid];
        xs4[tid + 64] = src[tid + 64];
        __syncthreads();

        #pragma unroll 2
        for (int jj = 0; jj < CHUNK / 4; jj++) {
            float4 xq = xs4[jj];

            #define SUBSTEP(XV, KEEP)                                          \
            {                                                                  \
                float u = fmaf((XV), wd, bd);                                  \
                ull u2 = bcast2(u);                                            \
                v2[0] = fma2(a2[0], v2[0], u2);                                \
                v2[1] = fma2(a2[1], v2[1], u2);                                \
                v2[2] = fma2(a2[2], v2[2], u2);                                \
                v2[3] = fma2(a2[3], v2[3], u2);                                \
                v2[4] = fma2(a2[4], v2[4], u2);                                \
                v2[5] = fma2(a2[5], v2[5], u2);                                \
                v2[6] = fma2(a2[6], v2[6], u2);                                \
                v2[7] = fma2(a2[7], v2[7], u2);                                \
                ull p0 = mul2(cb2[0], v2[0]);                                  \
                ull p1 = mul2(cb2[1], v2[1]);                                  \
                p0 = fma2(cb2[2], v2[2], p0);                                  \
                p1 = fma2(cb2[3], v2[3], p1);                                  \
                p0 = fma2(cb2[4], v2[4], p0);                                  \
                p1 = fma2(cb2[5], v2[5], p1);                                  \
                p0 = fma2(cb2[6], v2[6], p0);                                  \
                p1 = fma2(cb2[7], v2[7], p1);                                  \
                float2 pf = unpack2(add2(p0, p1));                             \
                float ps = pf.x + pf.y;                                        \
                ps += __shfl_xor_sync(0xffffffffu, ps, 1);                     \
                ps += __shfl_xor_sync(0xffffffffu, ps, 2);                     \
                float yv = fmaf(dsk, u, ps);                                   \
                ykeep = (KEEP) ? yv : ykeep;                                   \
            }

            SUBSTEP(xq.x, is0)
            SUBSTEP(xq.y, is1)
            SUBSTEP(xq.z, is2)
            SUBSTEP(xq.w, is3)
            #undef SUBSTEP

            // phase-distributed gelu: lane q handled timestep t0+4*jj+q
            float h = gelu_tanh(ykeep);
            asum += h;
            amax = fmaxf(amax, h);
        }
        __syncthreads();
    }

    // combine the 4 lanes' phase-partial accumulators
    asum += __shfl_xor_sync(0xffffffffu, asum, 1);
    asum += __shfl_xor_sync(0xffffffffu, asum, 2);
    amax = fmaxf(amax, __shfl_xor_sync(0xffffffffu, amax, 1));
    amax = fmaxf(amax, __shfl_xor_sync(0xffffffffu, amax, 2));

    if (is0) {
        g_pooled[b * (2 * DMODEL) + d]          = asum * (1.0f / T_LEN);
        g_pooled[b * (2 * DMODEL) + DMODEL + d] = amax;
    }
}

// one warp per (b, class): dot(pooled[b,:512], W_head[:,c]) + b_head[c]
__global__ void __launch_bounds__(32)
head_kernel(const float* __restrict__ W_head,
            const float* __restrict__ b_head,
            float* __restrict__ out)
{
    const int b = blockIdx.x / 5;
    const int c = blockIdx.x % 5;
    const int lane = threadIdx.x;

    float p = 0.0f;
    const float* pb = g_pooled + b * (2 * DMODEL);
    #pragma unroll 4
    for (int k = lane; k < 2 * DMODEL; k += 32)
        p += pb[k] * W_head[k * 5 + c];

    #pragma unroll
    for (int m = 16; m >= 1; m >>= 1)
        p += __shfl_xor_sync(0xffffffffu, p, m);

    if (lane == 0) out[b * 5 + c] = p + b_head[c];
}

extern "C" void kernel_launch(void* const* d_in, const int* in_sizes, int n_in,
                              void* d_out, int out_size)
{
    const float* x      = (const float*)d_in[0];  // [32, 4096]
    const float* w_in   = (const float*)d_in[1];  // [256]
    const float* b_in   = (const float*)d_in[2];  // [256]
    const float* A_diag = (const float*)d_in[3];  // [256, 64]
    const float* B_in   = (const float*)d_in[4];  // [256, 64]
    const float* C_out  = (const float*)d_in[5];  // [256, 64]
    const float* D_skip = (const float*)d_in[6];  // [256]
    const float* W_head = (const float*)d_in[7];  // [512, 5]
    const float* b_head = (const float*)d_in[8];  // [5]
    float* out = (float*)d_out;                   // [32, 5]

    ssm_scan_kernel<<<512, 64>>>(x, w_in, b_in, A_diag, B_in, C_out, D_skip);
    head_kernel<<<BATCH * 5, 32>>>(W_head, b_head, out);
}